// round 4
// baseline (speedup 1.0000x reference)
#include <cuda_runtime.h>
#include <cstdint>

// ---------------------------------------------------------------------------
// B=64, L=512, Din=256, Dout=256, split=128
//   G = inp @ [Wr|Wz|Wh] + bias   (precomputed)
//   a = sigmoid(x@(k1-k2))        (precomputed)
//   recurrence: mt -> S = mt@[Ur|Uz|Uh] -> gates -> h
// Recurrence: 32 clusters x 4 CTAs, U in registers, mbarrier sync,
// coref prefetched one step ahead.
// ---------------------------------------------------------------------------

#define B_  64
#define L_  512
#define D_  256

__device__ float g_G[(size_t)B_ * L_ * 768];     // ~100.7 MB
__device__ float g_A[(size_t)B_ * L_];           // 128 KB
__device__ float g_hist[(size_t)L_ * B_ * 128];  // upper half of h history, 16 MB

// ---------------------------------------------------------------------------
// helpers
// ---------------------------------------------------------------------------
__device__ __forceinline__ unsigned long long ffma2(
    unsigned long long a, unsigned long long b, unsigned long long c)
{
    unsigned long long d;
    asm("fma.rn.f32x2 %0, %1, %2, %3;" : "=l"(d) : "l"(a), "l"(b), "l"(c));
    return d;
}
__device__ __forceinline__ unsigned long long pack2(float x, float y) {
    unsigned long long r;
    asm("mov.b64 %0, {%1, %2};" : "=l"(r) : "f"(x), "f"(y));
    return r;
}
__device__ __forceinline__ void unpack2(unsigned long long v, float& x, float& y) {
    asm("mov.b64 {%0, %1}, %2;" : "=f"(x), "=f"(y) : "l"(v));
}
__device__ __forceinline__ float hadd2(unsigned long long v) {
    float x, y; unpack2(v, x, y); return x + y;
}
__device__ __forceinline__ unsigned smem_u32(const void* p) {
    unsigned a;
    asm("{ .reg .u64 t; cvta.to.shared.u64 t, %1; cvt.u32.u64 %0, t; }" : "=r"(a) : "l"(p));
    return a;
}
__device__ __forceinline__ void mbar_init(unsigned mbar, unsigned cnt) {
    asm volatile("mbarrier.init.shared.b64 [%0], %1;" :: "r"(mbar), "r"(cnt) : "memory");
}
__device__ __forceinline__ void mbar_arrive_remote(unsigned laddr, unsigned rank) {
    asm volatile(
        "{ .reg .b32 ra;\n\t"
        "  mapa.shared::cluster.u32 ra, %0, %1;\n\t"
        "  mbarrier.arrive.release.cluster.shared::cluster.b64 _, [ra]; }"
        :: "r"(laddr), "r"(rank) : "memory");
}
__device__ __forceinline__ void mbar_wait_cluster(unsigned mbar, unsigned parity) {
    asm volatile(
        "{\n\t.reg .pred P;\n\t"
        "WL%=:\n\t"
        "mbarrier.try_wait.parity.acquire.cluster.shared::cta.b64 P, [%0], %1, 0x989680;\n\t"
        "@!P bra WL%=;\n\t}"
        :: "r"(mbar), "r"(parity) : "memory");
}

// ---------------------------------------------------------------------------
// Kernel 1: G = inp @ Wcat + bias.  128x128x16 fp32 tiles, f32x2 FMA.
// ---------------------------------------------------------------------------
__global__ void __launch_bounds__(256) gemm_pre(
    const float* __restrict__ inp,
    const float* __restrict__ Wr, const float* __restrict__ Wz, const float* __restrict__ Wh,
    const float* __restrict__ br, const float* __restrict__ bz, const float* __restrict__ bh)
{
    __shared__ float As[16][132];
    __shared__ __align__(16) float Bs[16][128];

    const int ntile = blockIdx.x;
    const int mtile = blockIdx.y;
    const int gate  = ntile >> 1;
    const int ncol0 = (ntile & 1) * 128;
    const float* W    = (gate == 0) ? Wr : (gate == 1) ? Wz : Wh;
    const float* bias = (gate == 0) ? br : (gate == 1) ? bz : bh;

    const int tid = threadIdx.x;
    const int tm  = (tid >> 4) * 8;
    const int tn  = (tid & 15) * 8;

    const float* Ag = inp + (size_t)mtile * 128 * D_;
    const float* Bg = W + ncol0;

    const int a_row = tid >> 2;
    const int a_col = (tid & 3) * 4;
    const int b_row = tid >> 5;
    const int b_col = (tid & 31) * 4;

    unsigned long long acc2[8][4];
#pragma unroll
    for (int i = 0; i < 8; ++i)
#pragma unroll
        for (int q = 0; q < 4; ++q) acc2[i][q] = 0ull;

    for (int k0 = 0; k0 < D_; k0 += 16) {
        float4 a0  = *(const float4*)(Ag + (size_t)a_row        * D_ + k0 + a_col);
        float4 a1  = *(const float4*)(Ag + (size_t)(a_row + 64) * D_ + k0 + a_col);
        float4 bv0 = *(const float4*)(Bg + (size_t)(k0 + b_row)     * D_ + b_col);
        float4 bv1 = *(const float4*)(Bg + (size_t)(k0 + b_row + 8) * D_ + b_col);

        __syncthreads();
        As[a_col + 0][a_row] = a0.x; As[a_col + 1][a_row] = a0.y;
        As[a_col + 2][a_row] = a0.z; As[a_col + 3][a_row] = a0.w;
        As[a_col + 0][a_row + 64] = a1.x; As[a_col + 1][a_row + 64] = a1.y;
        As[a_col + 2][a_row + 64] = a1.z; As[a_col + 3][a_row + 64] = a1.w;
        *(float4*)&Bs[b_row][b_col]     = bv0;
        *(float4*)&Bs[b_row + 8][b_col] = bv1;
        __syncthreads();

#pragma unroll
        for (int k = 0; k < 16; ++k) {
            float4 af0 = *(const float4*)&As[k][tm];
            float4 af1 = *(const float4*)&As[k][tm + 4];
            const ulonglong2* bp = (const ulonglong2*)&Bs[k][tn];
            ulonglong2 bA = bp[0], bB = bp[1];
            float am[8] = {af0.x, af0.y, af0.z, af0.w, af1.x, af1.y, af1.z, af1.w};
#pragma unroll
            for (int i = 0; i < 8; ++i) {
                unsigned long long ad = pack2(am[i], am[i]);
                acc2[i][0] = ffma2(ad, bA.x, acc2[i][0]);
                acc2[i][1] = ffma2(ad, bA.y, acc2[i][1]);
                acc2[i][2] = ffma2(ad, bB.x, acc2[i][2]);
                acc2[i][3] = ffma2(ad, bB.y, acc2[i][3]);
            }
        }
    }

    float bb[8];
#pragma unroll
    for (int jj = 0; jj < 8; ++jj) bb[jj] = bias[ncol0 + tn + jj];

    const size_t ng0 = (size_t)gate * 256 + ncol0 + tn;
#pragma unroll
    for (int i = 0; i < 8; ++i) {
        size_t m = (size_t)mtile * 128 + tm + i;
        float o[8];
#pragma unroll
        for (int q = 0; q < 4; ++q) unpack2(acc2[i][q], o[2 * q], o[2 * q + 1]);
#pragma unroll
        for (int jj = 0; jj < 8; ++jj) o[jj] += bb[jj];
        *(float4*)&g_G[m * 768 + ng0]     = make_float4(o[0], o[1], o[2], o[3]);
        *(float4*)&g_G[m * 768 + ng0 + 4] = make_float4(o[4], o[5], o[6], o[7]);
    }
}

// ---------------------------------------------------------------------------
// Kernel 2: a[m] = sigmoid(x[m] . (k1 - k2))
// ---------------------------------------------------------------------------
__global__ void __launch_bounds__(256) avals_kernel(
    const float* __restrict__ inp,
    const float* __restrict__ k1, const float* __restrict__ k2)
{
    const int warp = threadIdx.x >> 5, lane = threadIdx.x & 31;
    const int m = blockIdx.x * 8 + warp;
    const float* x = inp + (size_t)m * D_;
    float s = 0.f;
#pragma unroll
    for (int i = lane; i < D_; i += 32) s += x[i] * (k1[i] - k2[i]);
#pragma unroll
    for (int o = 16; o; o >>= 1) s += __shfl_xor_sync(0xFFFFFFFFu, s, o);
    if (lane == 0) g_A[m] = 1.f / (1.f + __expf(-s));
}

// ---------------------------------------------------------------------------
// Kernel 3: recurrence. 32 clusters x 4 CTAs; CTA rank r owns cols [64r,64r+64).
// U in registers (f32x2). Per-step sync = mbarrier (16 arrivals: 4 warps x 4 CTAs).
// coref values prefetched one step ahead; ci & a staged in smem.
// ---------------------------------------------------------------------------
__global__ void __launch_bounds__(256, 1) __cluster_dims__(4, 1, 1)
recur_kernel(const float* __restrict__ Ur, const float* __restrict__ Uz,
             const float* __restrict__ Uh, const int* __restrict__ ci,
             float* __restrict__ out)
{
    __shared__ __align__(16) float mts[2 * 256];          // [b][k]
    __shared__ __align__(16) float hbuf[2 * 2 * 256];     // [phase][b][d] (full h)
    __shared__ __align__(16) float part[4 * 3 * 2 * 64];  // [kq][g][b][j]
    __shared__ __align__(16) float a_s[2 * 512];          // a values
    __shared__ __align__(16) int   ci_s[2 * 512];         // coref indices
    __shared__ __align__(8)  unsigned long long mbar_s;

    const int tid  = threadIdx.x;
    const int rank = blockIdx.x & 3;
    const int grp  = blockIdx.x >> 2;
    const int b0   = grp * 2;
    const int dg0  = rank * 64;

    const int j  = tid & 63;          // GEMM column
    const int kq = tid >> 6;          // GEMM k-quarter
    const int k0 = kq * 64;

    // ---- one-time loads: U slice into registers, a/ci into smem ----
    unsigned long long u0[32], u1[32], u2[32];
    {
        const float* pr = Ur + (size_t)k0 * D_ + dg0 + j;
        const float* pz = Uz + (size_t)k0 * D_ + dg0 + j;
        const float* ph = Uh + (size_t)k0 * D_ + dg0 + j;
#pragma unroll
        for (int i = 0; i < 32; ++i) {
            u0[i] = pack2(pr[(2 * i) * D_], pr[(2 * i + 1) * D_]);
            u1[i] = pack2(pz[(2 * i) * D_], pz[(2 * i + 1) * D_]);
            u2[i] = pack2(ph[(2 * i) * D_], ph[(2 * i + 1) * D_]);
        }
    }
    {
        const float4* ga = (const float4*)&g_A[(size_t)b0 * L_];
        const int4*   gc = (const int4*)  (ci + (size_t)b0 * L_);
        ((float4*)a_s)[tid] = ga[tid];
        ((int4*)ci_s)[tid]  = gc[tid];
    }
    for (int i = tid; i < 1024; i += 256) hbuf[i] = 0.f;
    if (tid == 0) mbar_init(smem_u32(&mbar_s), 16);
    __syncthreads();
    asm volatile("barrier.cluster.arrive.aligned;" ::: "memory");
    asm volatile("barrier.cluster.wait.aligned;" ::: "memory");

    const unsigned mbar = smem_u32(&mbar_s);

    // roles
    const int eb = tid >> 6;          // eltwise b (tid<128)
    const int ej = tid & 63;
    const int dg = dg0 + ej;
    const int bq = tid >> 7;          // mt-build / prefetch b
    const int dq = tid & 127;         // mt-build / prefetch d (hi col = 128+dq)

    // prefetch G for t=0 (tid<128)
    float gn0 = 0.f, gn1 = 0.f, gn2 = 0.f;
    if (tid < 128) {
        size_t gb = ((size_t)(b0 + eb) * L_) * 768 + dg;
        gn0 = g_G[gb]; gn1 = g_G[gb + 256]; gn2 = g_G[gb + 512];
    }

    // coref prefetch for t=0
    float vc = 0.f; int cflag = 0;
    {
        int c = ci_s[bq * L_];
        if (c > 0) vc = g_hist[(((size_t)(c - 1)) * B_ + b0 + bq) * 128 + dq];
    }

    for (int t = 0; t < L_; ++t) {
        const int p = t & 1;

        // ---- build mt[2][256]: lo from hbuf, hi from prefetched coref ----
        {
            float av = a_s[bq * L_ + t];
            float lo = av * hbuf[(p * 2 + bq) * 256 + dq];
            float cv = cflag ? hbuf[(p * 2 + bq) * 256 + 128 + dq] : vc;
            mts[bq * 256 + dq]       = lo;
            mts[bq * 256 + 128 + dq] = (1.f - av) * cv;
        }
        __syncthreads();

        // ---- GEMM: registers x smem-broadcast mt, packed f32x2 ----
        unsigned long long a00 = 0ull, a01 = 0ull;
        unsigned long long a10 = 0ull, a11 = 0ull;
        unsigned long long a20 = 0ull, a21 = 0ull;
        {
            const ulonglong2* m0 = (const ulonglong2*)&mts[k0];
            const ulonglong2* m1 = (const ulonglong2*)&mts[256 + k0];
#pragma unroll
            for (int i = 0; i < 16; ++i) {
                ulonglong2 v0 = m0[i];
                ulonglong2 v1 = m1[i];
                a00 = ffma2(u0[2 * i], v0.x, a00);
                a01 = ffma2(u0[2 * i], v1.x, a01);
                a10 = ffma2(u1[2 * i], v0.x, a10);
                a11 = ffma2(u1[2 * i], v1.x, a11);
                a20 = ffma2(u2[2 * i], v0.x, a20);
                a21 = ffma2(u2[2 * i], v1.x, a21);
                a00 = ffma2(u0[2 * i + 1], v0.y, a00);
                a01 = ffma2(u0[2 * i + 1], v1.y, a01);
                a10 = ffma2(u1[2 * i + 1], v0.y, a10);
                a11 = ffma2(u1[2 * i + 1], v1.y, a11);
                a20 = ffma2(u2[2 * i + 1], v0.y, a20);
                a21 = ffma2(u2[2 * i + 1], v1.y, a21);
            }
        }
        part[((kq * 3 + 0) * 2 + 0) * 64 + j] = hadd2(a00);
        part[((kq * 3 + 0) * 2 + 1) * 64 + j] = hadd2(a01);
        part[((kq * 3 + 1) * 2 + 0) * 64 + j] = hadd2(a10);
        part[((kq * 3 + 1) * 2 + 1) * 64 + j] = hadd2(a11);
        part[((kq * 3 + 2) * 2 + 0) * 64 + j] = hadd2(a20);
        part[((kq * 3 + 2) * 2 + 1) * 64 + j] = hadd2(a21);
        __syncthreads();

        // ---- elementwise + broadcast (tid < 128) ----
        if (tid < 128) {
            float Sr = 0.f, Sz = 0.f, Sh = 0.f;
#pragma unroll
            for (int q = 0; q < 4; ++q) {
                Sr += part[((q * 3 + 0) * 2 + eb) * 64 + ej];
                Sz += part[((q * 3 + 1) * 2 + eb) * 64 + ej];
                Sh += part[((q * 3 + 2) * 2 + eb) * 64 + ej];
            }
            float r  = 1.f / (1.f + __expf(-(gn0 + Sr)));
            float z  = 1.f / (1.f + __expf(-(gn1 + Sz)));
            float ti = gn2 + r * Sh;
            float th = 2.f / (1.f + __expf(-2.f * ti)) - 1.f;
            float mtd = mts[eb * 256 + dg];
            float h = (1.f - z) * mtd + z * th;

            out[(((size_t)(b0 + eb)) * L_ + t) * D_ + dg] = h;
            if (dg >= 128)
                g_hist[((size_t)t * B_ + b0 + eb) * 128 + dg - 128] = h;

            // full-h broadcast to all 4 CTAs' hbuf (phase p^1)
            unsigned laddr = smem_u32(&hbuf[((p ^ 1) * 2 + eb) * 256 + dg]);
#pragma unroll
            for (int rr = 0; rr < 4; ++rr)
                asm volatile(
                    "{ .reg .b32 ra; mapa.shared::cluster.u32 ra, %0, %1;"
                    "  st.shared::cluster.f32 [ra], %2; }"
                    :: "r"(laddr), "r"(rr), "f"(h));

            __syncwarp();
            if ((tid & 31) == 0) {
#pragma unroll
                for (int rr = 0; rr < 4; ++rr) mbar_arrive_remote(mbar, rr);
            }

            // prefetch G for next step
            int tn = (t + 1 < L_) ? (t + 1) : (L_ - 1);
            size_t gb = ((size_t)(b0 + eb) * L_ + tn) * 768 + dg;
            gn0 = g_G[gb]; gn1 = g_G[gb + 256]; gn2 = g_G[gb + 512];
        }

        // ---- coref prefetch for step t+1 (all threads) ----
        if (t + 1 < L_) {
            int c = ci_s[bq * L_ + t + 1];
            cflag = (c > 0) && (c - 1 == t);
            vc = 0.f;
            if (c > 0 && !cflag)
                vc = g_hist[(((size_t)(c - 1)) * B_ + b0 + bq) * 128 + dq];
        }

        mbar_wait_cluster(mbar, t & 1);
    }
}

// ---------------------------------------------------------------------------
// launch
// ---------------------------------------------------------------------------
extern "C" void kernel_launch(void* const* d_in, const int* in_sizes, int n_in,
                              void* d_out, int out_size)
{
    const float* inp = (const float*)d_in[0];
    const int*   ci  = (const int*)  d_in[1];
    const float* Wr  = (const float*)d_in[2];
    const float* br  = (const float*)d_in[3];
    const float* Ur  = (const float*)d_in[4];
    const float* Wz  = (const float*)d_in[5];
    const float* bz  = (const float*)d_in[6];
    const float* Uz  = (const float*)d_in[7];
    const float* Wh  = (const float*)d_in[8];
    const float* bh  = (const float*)d_in[9];
    const float* Uh  = (const float*)d_in[10];
    const float* k1  = (const float*)d_in[11];
    const float* k2  = (const float*)d_in[12];
    float* out = (float*)d_out;

    gemm_pre<<<dim3(6, (B_ * L_) / 128), 256>>>(inp, Wr, Wz, Wh, br, bz, bh);
    avals_kernel<<<(B_ * L_) / 8, 256>>>(inp, k1, k2);
    recur_kernel<<<128, 256>>>(Ur, Uz, Uh, ci, out);
}

// round 5
// speedup vs baseline: 1.1931x; 1.1931x over previous
#include <cuda_runtime.h>
#include <cstdint>

// ---------------------------------------------------------------------------
// B=64, L=512, Din=256, Dout=256, split=128
//   G = inp @ [Wr|Wz|Wh] + bias   (precomputed)
//   a = sigmoid(x@(k1-k2))        (precomputed)
//   recurrence: mt -> S = mt@[Ur|Uz|Uh] -> gates -> h
// Recurrence: 32 clusters x 4 CTAs, U in registers, mbarrier sync
// (release.cluster arrive / acquire.cta wait), coref prefetched 1 step ahead.
// ---------------------------------------------------------------------------

#define B_  64
#define L_  512
#define D_  256

__device__ float g_G[(size_t)B_ * L_ * 768];     // ~100.7 MB
__device__ float g_A[(size_t)B_ * L_];           // 128 KB
__device__ float g_hist[(size_t)L_ * B_ * 128];  // upper half of h history, 16 MB

// ---------------------------------------------------------------------------
// helpers
// ---------------------------------------------------------------------------
__device__ __forceinline__ unsigned long long ffma2(
    unsigned long long a, unsigned long long b, unsigned long long c)
{
    unsigned long long d;
    asm("fma.rn.f32x2 %0, %1, %2, %3;" : "=l"(d) : "l"(a), "l"(b), "l"(c));
    return d;
}
__device__ __forceinline__ unsigned long long pack2(float x, float y) {
    unsigned long long r;
    asm("mov.b64 %0, {%1, %2};" : "=l"(r) : "f"(x), "f"(y));
    return r;
}
__device__ __forceinline__ void unpack2(unsigned long long v, float& x, float& y) {
    asm("mov.b64 {%0, %1}, %2;" : "=f"(x), "=f"(y) : "l"(v));
}
__device__ __forceinline__ float hadd2(unsigned long long v) {
    float x, y; unpack2(v, x, y); return x + y;
}
__device__ __forceinline__ unsigned smem_u32(const void* p) {
    unsigned a;
    asm("{ .reg .u64 t; cvta.to.shared.u64 t, %1; cvt.u32.u64 %0, t; }" : "=r"(a) : "l"(p));
    return a;
}
__device__ __forceinline__ void mbar_init(unsigned mbar, unsigned cnt) {
    asm volatile("mbarrier.init.shared.b64 [%0], %1;" :: "r"(mbar), "r"(cnt) : "memory");
}
__device__ __forceinline__ void mbar_arrive_remote(unsigned laddr, unsigned rank) {
    asm volatile(
        "{ .reg .b32 ra;\n\t"
        "  mapa.shared::cluster.u32 ra, %0, %1;\n\t"
        "  mbarrier.arrive.release.cluster.shared::cluster.b64 _, [ra]; }"
        :: "r"(laddr), "r"(rank) : "memory");
}
__device__ __forceinline__ void mbar_wait_cta(unsigned mbar, unsigned parity) {
    asm volatile(
        "{\n\t.reg .pred P;\n\t"
        "WL%=:\n\t"
        "mbarrier.try_wait.parity.acquire.cta.shared::cta.b64 P, [%0], %1, 0x989680;\n\t"
        "@!P bra WL%=;\n\t}"
        :: "r"(mbar), "r"(parity) : "memory");
}

// ---------------------------------------------------------------------------
// Kernel 1: G = inp @ Wcat + bias.  128x128x16 fp32 tiles, f32x2 FMA.
// ---------------------------------------------------------------------------
__global__ void __launch_bounds__(256) gemm_pre(
    const float* __restrict__ inp,
    const float* __restrict__ Wr, const float* __restrict__ Wz, const float* __restrict__ Wh,
    const float* __restrict__ br, const float* __restrict__ bz, const float* __restrict__ bh)
{
    __shared__ float As[16][132];
    __shared__ __align__(16) float Bs[16][128];

    const int ntile = blockIdx.x;
    const int mtile = blockIdx.y;
    const int gate  = ntile >> 1;
    const int ncol0 = (ntile & 1) * 128;
    const float* W    = (gate == 0) ? Wr : (gate == 1) ? Wz : Wh;
    const float* bias = (gate == 0) ? br : (gate == 1) ? bz : bh;

    const int tid = threadIdx.x;
    const int tm  = (tid >> 4) * 8;
    const int tn  = (tid & 15) * 8;

    const float* Ag = inp + (size_t)mtile * 128 * D_;
    const float* Bg = W + ncol0;

    const int a_row = tid >> 2;
    const int a_col = (tid & 3) * 4;
    const int b_row = tid >> 5;
    const int b_col = (tid & 31) * 4;

    unsigned long long acc2[8][4];
#pragma unroll
    for (int i = 0; i < 8; ++i)
#pragma unroll
        for (int q = 0; q < 4; ++q) acc2[i][q] = 0ull;

    for (int k0 = 0; k0 < D_; k0 += 16) {
        float4 a0  = *(const float4*)(Ag + (size_t)a_row        * D_ + k0 + a_col);
        float4 a1  = *(const float4*)(Ag + (size_t)(a_row + 64) * D_ + k0 + a_col);
        float4 bv0 = *(const float4*)(Bg + (size_t)(k0 + b_row)     * D_ + b_col);
        float4 bv1 = *(const float4*)(Bg + (size_t)(k0 + b_row + 8) * D_ + b_col);

        __syncthreads();
        As[a_col + 0][a_row] = a0.x; As[a_col + 1][a_row] = a0.y;
        As[a_col + 2][a_row] = a0.z; As[a_col + 3][a_row] = a0.w;
        As[a_col + 0][a_row + 64] = a1.x; As[a_col + 1][a_row + 64] = a1.y;
        As[a_col + 2][a_row + 64] = a1.z; As[a_col + 3][a_row + 64] = a1.w;
        *(float4*)&Bs[b_row][b_col]     = bv0;
        *(float4*)&Bs[b_row + 8][b_col] = bv1;
        __syncthreads();

#pragma unroll
        for (int k = 0; k < 16; ++k) {
            float4 af0 = *(const float4*)&As[k][tm];
            float4 af1 = *(const float4*)&As[k][tm + 4];
            const ulonglong2* bp = (const ulonglong2*)&Bs[k][tn];
            ulonglong2 bA = bp[0], bB = bp[1];
            float am[8] = {af0.x, af0.y, af0.z, af0.w, af1.x, af1.y, af1.z, af1.w};
#pragma unroll
            for (int i = 0; i < 8; ++i) {
                unsigned long long ad = pack2(am[i], am[i]);
                acc2[i][0] = ffma2(ad, bA.x, acc2[i][0]);
                acc2[i][1] = ffma2(ad, bA.y, acc2[i][1]);
                acc2[i][2] = ffma2(ad, bB.x, acc2[i][2]);
                acc2[i][3] = ffma2(ad, bB.y, acc2[i][3]);
            }
        }
    }

    float bb[8];
#pragma unroll
    for (int jj = 0; jj < 8; ++jj) bb[jj] = bias[ncol0 + tn + jj];

    const size_t ng0 = (size_t)gate * 256 + ncol0 + tn;
#pragma unroll
    for (int i = 0; i < 8; ++i) {
        size_t m = (size_t)mtile * 128 + tm + i;
        float o[8];
#pragma unroll
        for (int q = 0; q < 4; ++q) unpack2(acc2[i][q], o[2 * q], o[2 * q + 1]);
#pragma unroll
        for (int jj = 0; jj < 8; ++jj) o[jj] += bb[jj];
        *(float4*)&g_G[m * 768 + ng0]     = make_float4(o[0], o[1], o[2], o[3]);
        *(float4*)&g_G[m * 768 + ng0 + 4] = make_float4(o[4], o[5], o[6], o[7]);
    }
}

// ---------------------------------------------------------------------------
// Kernel 2: a[m] = sigmoid(x[m] . (k1 - k2))
// ---------------------------------------------------------------------------
__global__ void __launch_bounds__(256) avals_kernel(
    const float* __restrict__ inp,
    const float* __restrict__ k1, const float* __restrict__ k2)
{
    const int warp = threadIdx.x >> 5, lane = threadIdx.x & 31;
    const int m = blockIdx.x * 8 + warp;
    const float* x = inp + (size_t)m * D_;
    float s = 0.f;
#pragma unroll
    for (int i = lane; i < D_; i += 32) s += x[i] * (k1[i] - k2[i]);
#pragma unroll
    for (int o = 16; o; o >>= 1) s += __shfl_xor_sync(0xFFFFFFFFu, s, o);
    if (lane == 0) g_A[m] = 1.f / (1.f + __expf(-s));
}

// ---------------------------------------------------------------------------
// Kernel 3: recurrence. 32 clusters x 4 CTAs; CTA rank r owns cols [64r,64r+64).
// U in registers (f32x2). Per-step sync: 16-arrival mbarrier
// (arrive.release.cluster from producers, acquire.cta poll at consumers).
// ---------------------------------------------------------------------------
__global__ void __launch_bounds__(256, 1) __cluster_dims__(4, 1, 1)
recur_kernel(const float* __restrict__ Ur, const float* __restrict__ Uz,
             const float* __restrict__ Uh, const int* __restrict__ ci,
             float* __restrict__ out)
{
    __shared__ __align__(16) float mts[2 * 256];          // [b][k]
    __shared__ __align__(16) float hbuf[2 * 2 * 256];     // [phase][b][d] (full h)
    __shared__ __align__(16) float part[4 * 3 * 2 * 64];  // [kq][g][b][j]
    __shared__ __align__(16) float a_s[2 * 512];          // a values
    __shared__ __align__(16) int   ci_s[2 * 512];         // coref indices
    __shared__ __align__(8)  unsigned long long mbar_s;

    const int tid  = threadIdx.x;
    const int rank = blockIdx.x & 3;
    const int grp  = blockIdx.x >> 2;
    const int b0   = grp * 2;
    const int dg0  = rank * 64;

    const int j  = tid & 63;          // GEMM column
    const int kq = tid >> 6;          // GEMM k-quarter
    const int k0 = kq * 64;

    // ---- one-time loads: U slice into registers, a/ci into smem ----
    unsigned long long u0[32], u1[32], u2[32];
    {
        const float* pr = Ur + (size_t)k0 * D_ + dg0 + j;
        const float* pz = Uz + (size_t)k0 * D_ + dg0 + j;
        const float* ph = Uh + (size_t)k0 * D_ + dg0 + j;
#pragma unroll
        for (int i = 0; i < 32; ++i) {
            u0[i] = pack2(pr[(2 * i) * D_], pr[(2 * i + 1) * D_]);
            u1[i] = pack2(pz[(2 * i) * D_], pz[(2 * i + 1) * D_]);
            u2[i] = pack2(ph[(2 * i) * D_], ph[(2 * i + 1) * D_]);
        }
    }
    {
        const float4* ga = (const float4*)&g_A[(size_t)b0 * L_];
        const int4*   gc = (const int4*)  (ci + (size_t)b0 * L_);
        ((float4*)a_s)[tid] = ga[tid];
        ((int4*)ci_s)[tid]  = gc[tid];
    }
    for (int i = tid; i < 1024; i += 256) hbuf[i] = 0.f;
    if (tid == 0) mbar_init(smem_u32(&mbar_s), 16);
    __syncthreads();
    asm volatile("barrier.cluster.arrive.aligned;" ::: "memory");
    asm volatile("barrier.cluster.wait.aligned;" ::: "memory");

    const unsigned mbar = smem_u32(&mbar_s);

    // roles
    const int eb = tid >> 6;          // eltwise b (tid<128)
    const int ej = tid & 63;
    const int dg = dg0 + ej;
    const int bq = tid >> 7;          // mt-build / prefetch b
    const int dq = tid & 127;         // mt-build / prefetch d (hi col = 128+dq)

    // prefetch G for t=0 (tid<128)
    float gn0 = 0.f, gn1 = 0.f, gn2 = 0.f;
    if (tid < 128) {
        size_t gb = ((size_t)(b0 + eb) * L_) * 768 + dg;
        gn0 = g_G[gb]; gn1 = g_G[gb + 256]; gn2 = g_G[gb + 512];
    }

    // coref prefetch for t=0
    float vc = 0.f; int cflag = 0;
    {
        int c = ci_s[bq * L_];
        if (c > 0) vc = g_hist[(((size_t)(c - 1)) * B_ + b0 + bq) * 128 + dq];
    }

    for (int t = 0; t < L_; ++t) {
        const int p = t & 1;

        // ---- build mt[2][256]: lo from hbuf, hi from prefetched coref ----
        {
            float av = a_s[bq * L_ + t];
            float lo = av * hbuf[(p * 2 + bq) * 256 + dq];
            float cv = cflag ? hbuf[(p * 2 + bq) * 256 + 128 + dq] : vc;
            mts[bq * 256 + dq]       = lo;
            mts[bq * 256 + 128 + dq] = (1.f - av) * cv;
        }
        __syncthreads();

        // ---- GEMM: registers x smem-broadcast mt, packed f32x2 ----
        unsigned long long a00 = 0ull, a01 = 0ull;
        unsigned long long a10 = 0ull, a11 = 0ull;
        unsigned long long a20 = 0ull, a21 = 0ull;
        {
            const ulonglong2* m0 = (const ulonglong2*)&mts[k0];
            const ulonglong2* m1 = (const ulonglong2*)&mts[256 + k0];
#pragma unroll
            for (int i = 0; i < 16; ++i) {
                ulonglong2 v0 = m0[i];
                ulonglong2 v1 = m1[i];
                a00 = ffma2(u0[2 * i], v0.x, a00);
                a01 = ffma2(u0[2 * i], v1.x, a01);
                a10 = ffma2(u1[2 * i], v0.x, a10);
                a11 = ffma2(u1[2 * i], v1.x, a11);
                a20 = ffma2(u2[2 * i], v0.x, a20);
                a21 = ffma2(u2[2 * i], v1.x, a21);
                a00 = ffma2(u0[2 * i + 1], v0.y, a00);
                a01 = ffma2(u0[2 * i + 1], v1.y, a01);
                a10 = ffma2(u1[2 * i + 1], v0.y, a10);
                a11 = ffma2(u1[2 * i + 1], v1.y, a11);
                a20 = ffma2(u2[2 * i + 1], v0.y, a20);
                a21 = ffma2(u2[2 * i + 1], v1.y, a21);
            }
        }
        part[((kq * 3 + 0) * 2 + 0) * 64 + j] = hadd2(a00);
        part[((kq * 3 + 0) * 2 + 1) * 64 + j] = hadd2(a01);
        part[((kq * 3 + 1) * 2 + 0) * 64 + j] = hadd2(a10);
        part[((kq * 3 + 1) * 2 + 1) * 64 + j] = hadd2(a11);
        part[((kq * 3 + 2) * 2 + 0) * 64 + j] = hadd2(a20);
        part[((kq * 3 + 2) * 2 + 1) * 64 + j] = hadd2(a21);
        __syncthreads();

        // ---- elementwise + broadcast (tid < 128) ----
        if (tid < 128) {
            float Sr = 0.f, Sz = 0.f, Sh = 0.f;
#pragma unroll
            for (int q = 0; q < 4; ++q) {
                Sr += part[((q * 3 + 0) * 2 + eb) * 64 + ej];
                Sz += part[((q * 3 + 1) * 2 + eb) * 64 + ej];
                Sh += part[((q * 3 + 2) * 2 + eb) * 64 + ej];
            }
            float r  = 1.f / (1.f + __expf(-(gn0 + Sr)));
            float z  = 1.f / (1.f + __expf(-(gn1 + Sz)));
            float ti = gn2 + r * Sh;
            float th = 2.f / (1.f + __expf(-2.f * ti)) - 1.f;
            float mtd = mts[eb * 256 + dg];
            float h = (1.f - z) * mtd + z * th;

            // communication first: full-h broadcast to all 4 CTAs (phase p^1)
            unsigned laddr = smem_u32(&hbuf[((p ^ 1) * 2 + eb) * 256 + dg]);
#pragma unroll
            for (int rr = 0; rr < 4; ++rr)
                asm volatile(
                    "{ .reg .b32 ra; mapa.shared::cluster.u32 ra, %0, %1;"
                    "  st.shared::cluster.f32 [ra], %2; }"
                    :: "r"(laddr), "r"(rr), "f"(h));
            if (dg >= 128)
                g_hist[((size_t)t * B_ + b0 + eb) * 128 + dg - 128] = h;

            __syncwarp();
            if ((tid & 31) < 4) mbar_arrive_remote(mbar, tid & 31);

            // off-path stores & prefetch
            out[(((size_t)(b0 + eb)) * L_ + t) * D_ + dg] = h;
            int tn = (t + 1 < L_) ? (t + 1) : (L_ - 1);
            size_t gb = ((size_t)(b0 + eb) * L_ + tn) * 768 + dg;
            gn0 = g_G[gb]; gn1 = g_G[gb + 256]; gn2 = g_G[gb + 512];
        }

        // ---- coref prefetch for step t+1 (all threads) ----
        if (t + 1 < L_) {
            int c = ci_s[bq * L_ + t + 1];
            cflag = (c > 0) && (c - 1 == t);
            vc = 0.f;
            if (c > 0 && !cflag)
                vc = g_hist[(((size_t)(c - 1)) * B_ + b0 + bq) * 128 + dq];
        }

        mbar_wait_cta(mbar, t & 1);
    }
}

// ---------------------------------------------------------------------------
// launch
// ---------------------------------------------------------------------------
extern "C" void kernel_launch(void* const* d_in, const int* in_sizes, int n_in,
                              void* d_out, int out_size)
{
    const float* inp = (const float*)d_in[0];
    const int*   ci  = (const int*)  d_in[1];
    const float* Wr  = (const float*)d_in[2];
    const float* br  = (const float*)d_in[3];
    const float* Ur  = (const float*)d_in[4];
    const float* Wz  = (const float*)d_in[5];
    const float* bz  = (const float*)d_in[6];
    const float* Uz  = (const float*)d_in[7];
    const float* Wh  = (const float*)d_in[8];
    const float* bh  = (const float*)d_in[9];
    const float* Uh  = (const float*)d_in[10];
    const float* k1  = (const float*)d_in[11];
    const float* k2  = (const float*)d_in[12];
    float* out = (float*)d_out;

    gemm_pre<<<dim3(6, (B_ * L_) / 128), 256>>>(inp, Wr, Wz, Wh, br, bz, bh);
    avals_kernel<<<(B_ * L_) / 8, 256>>>(inp, k1, k2);
    recur_kernel<<<128, 256>>>(Ur, Uz, Uh, ci, out);
}